// round 5
// baseline (speedup 1.0000x reference)
#include <cuda_runtime.h>
#include <cstdint>

// InteractingSites: per-frame all-pairs soft-core Coulomb.
// Packed-f32x2 distance math + SCALAR rsqrt/accumulate finish (no repack),
// 4 warps per frame, barrier-free entry (all warps build identical j-tables).
//
// energy[f] = sum_{i<j} q_i q_j * rsqrt(|p_i-p_j|^2 + 1e-6)
//
// Tiles T0..T3 of 32 sites; lane l holds rows T0[l]..T3[l]. Packed row regs:
//   ab=(T0,T1)  ac=(T0,T2)  cd=(T2,T3)
// Scalar accumulators per stream half: a0l/a0h (ab), a1l/a1h (ac), a2l/a2h (cd)
// hold sum_j q_j * rsqrt(...); row charges applied once at the end:
//   E_lane = q0*(a0l+a1l) + q1*a0h + q2*(a1h+a2l) + q3*a2h
//
// Enumeration (each unordered pair exactly once), split across 4 warps:
//  Rectangles (warp-uniform m, broadcast LDS), warp w: m in [8w, 8w+8):
//    g1: ab vs dup(T2[m])   g2: ab vs dup(T3[m])   g3: ac vs (T1[m],T3[m])
//  Triangles (lane-varying m=(l+dd)&31, SoA LDS):
//    warps 0..2: dd in [1+4w, 5+4w); warp 3: dd 13..15 + masked dd=16.

#define S_SITES 128
#define EPS2_PACKED 0x358637BD358637BDULL  // (1e-6f, 1e-6f)

using u64 = unsigned long long;

__device__ __forceinline__ u64 pk2(float lo, float hi) {
    u64 r;
    asm("mov.b64 %0, {%1, %2};" : "=l"(r) : "f"(lo), "f"(hi));
    return r;
}
__device__ __forceinline__ void unpk2(u64 v, float& lo, float& hi) {
    asm("mov.b64 {%0, %1}, %2;" : "=f"(lo), "=f"(hi) : "l"(v));
}
__device__ __forceinline__ u64 add2(u64 a, u64 b) {
    u64 d;
    asm("add.rn.f32x2 %0, %1, %2;" : "=l"(d) : "l"(a), "l"(b));
    return d;
}
__device__ __forceinline__ u64 fma2(u64 a, u64 b, u64 c) {
    u64 d;
    asm("fma.rn.f32x2 %0, %1, %2, %3;" : "=l"(d) : "l"(a), "l"(b), "l"(c));
    return d;
}
__device__ __forceinline__ float frsqrt(float x) {
    float r;
    asm("rsqrt.approx.f32 %0, %1;" : "=f"(r) : "f"(x));
    return r;
}

// rows (rx,ry,rz) vs j (jx,jy,jz negated; jq = packed charge pair read as 2
// scalars). Packed r2, scalar rsqrt + accumulate (no repack).
__device__ __forceinline__ void grp(u64 rx, u64 ry, u64 rz,
                                    u64 jx, u64 jy, u64 jz, u64 jq,
                                    float& al, float& ah) {
    u64 dx = add2(rx, jx);
    u64 dy = add2(ry, jy);
    u64 dz = add2(rz, jz);
    u64 r2 = fma2(dz, dz, (u64)EPS2_PACKED);
    r2 = fma2(dy, dy, r2);
    r2 = fma2(dx, dx, r2);
    float r2l, r2h, ql, qh;
    unpk2(r2, r2l, r2h);
    unpk2(jq, ql, qh);
    al = fmaf(ql, frsqrt(r2l), al);
    ah = fmaf(qh, frsqrt(r2h), ah);
}

__global__ __launch_bounds__(S_SITES)
void interacting_sites_kernel(const float* __restrict__ positions,
                              const float* __restrict__ charges,
                              float* __restrict__ out) {
    // AoS (broadcast, rect): [0:dupT2, 1:dupT3, 2:(T1,T3)][m][xx,yy,zz,qq]
    __shared__ u64 aos[3][32][4];
    // SoA (lane-varying, tri): [0:(T0,T1), 1:(T2,T3)][xx,yy,zz,qq][m]
    __shared__ u64 soa[2][4][32];
    __shared__ float warp_sum[4];

    const int fid = blockIdx.x;
    const int w = threadIdx.x >> 5;
    const int l = threadIdx.x & 31;

    // Every warp loads the full 4x32 site table into registers
    const long long base = (long long)fid * S_SITES;
    float sx[4], sy[4], sz[4], sq[4];
#pragma unroll
    for (int k = 0; k < 4; ++k) {
        const long long idx = base + k * 32 + l;
        const float* p = positions + idx * 3;
        sx[k] = p[0];
        sy[k] = p[1];
        sz[k] = p[2];
        sq[k] = charges[idx];
    }

    // EVERY warp writes the (identical) j-tables: benign same-value race,
    // so no cross-warp barrier is needed — only __syncwarp below.
    aos[0][l][0] = pk2(-sx[2], -sx[2]);
    aos[0][l][1] = pk2(-sy[2], -sy[2]);
    aos[0][l][2] = pk2(-sz[2], -sz[2]);
    aos[0][l][3] = pk2( sq[2],  sq[2]);
    aos[1][l][0] = pk2(-sx[3], -sx[3]);
    aos[1][l][1] = pk2(-sy[3], -sy[3]);
    aos[1][l][2] = pk2(-sz[3], -sz[3]);
    aos[1][l][3] = pk2( sq[3],  sq[3]);
    aos[2][l][0] = pk2(-sx[1], -sx[3]);
    aos[2][l][1] = pk2(-sy[1], -sy[3]);
    aos[2][l][2] = pk2(-sz[1], -sz[3]);
    aos[2][l][3] = pk2( sq[1],  sq[3]);
    soa[0][0][l] = pk2(-sx[0], -sx[1]);
    soa[0][1][l] = pk2(-sy[0], -sy[1]);
    soa[0][2][l] = pk2(-sz[0], -sz[1]);
    soa[0][3][l] = pk2( sq[0],  sq[1]);
    soa[1][0][l] = pk2(-sx[2], -sx[3]);
    soa[1][1][l] = pk2(-sy[2], -sy[3]);
    soa[1][2][l] = pk2(-sz[2], -sz[3]);
    soa[1][3][l] = pk2( sq[2],  sq[3]);
    __syncwarp();

    const u64 ab_x = pk2(sx[0], sx[1]), ab_y = pk2(sy[0], sy[1]), ab_z = pk2(sz[0], sz[1]);
    const u64 ac_x = pk2(sx[0], sx[2]), ac_y = pk2(sy[0], sy[2]), ac_z = pk2(sz[0], sz[2]);
    const u64 cd_x = pk2(sx[2], sx[3]), cd_y = pk2(sy[2], sy[3]), cd_z = pk2(sz[2], sz[3]);

    float a0l = 0.f, a0h = 0.f, a1l = 0.f, a1h = 0.f, a2l = 0.f, a2h = 0.f;

    // ── Rectangles: this warp handles m in [8w, 8w+8) ──
    const int m0 = w << 3;
#pragma unroll
    for (int i = 0; i < 8; ++i) {
        const int m = m0 + i;
        {
            const ulonglong2 jxy = *reinterpret_cast<const ulonglong2*>(&aos[0][m][0]);
            const ulonglong2 jzq = *reinterpret_cast<const ulonglong2*>(&aos[0][m][2]);
            grp(ab_x, ab_y, ab_z, jxy.x, jxy.y, jzq.x, jzq.y, a0l, a0h);
        }
        {
            const ulonglong2 jxy = *reinterpret_cast<const ulonglong2*>(&aos[1][m][0]);
            const ulonglong2 jzq = *reinterpret_cast<const ulonglong2*>(&aos[1][m][2]);
            grp(ab_x, ab_y, ab_z, jxy.x, jxy.y, jzq.x, jzq.y, a0l, a0h);
        }
        {
            const ulonglong2 jxy = *reinterpret_cast<const ulonglong2*>(&aos[2][m][0]);
            const ulonglong2 jzq = *reinterpret_cast<const ulonglong2*>(&aos[2][m][2]);
            grp(ac_x, ac_y, ac_z, jxy.x, jxy.y, jzq.x, jzq.y, a1l, a1h);
        }
    }

    // ── Triangles: warps 0..2 take dd in [1+4w,5+4w); warp 3: 13..15 + dd=16 ──
    const int dd0 = 1 + (w << 2);
#pragma unroll
    for (int i = 0; i < 4; ++i) {
        const int dd = dd0 + i;
        if (dd < 16) {
            const int m = (l + dd) & 31;
            grp(ab_x, ab_y, ab_z,
                soa[0][0][m], soa[0][1][m], soa[0][2][m], soa[0][3][m], a0l, a0h);
            grp(cd_x, cd_y, cd_z,
                soa[1][0][m], soa[1][1][m], soa[1][2][m], soa[1][3][m], a2l, a2h);
        }
    }
    if (w == 3 && l < 16) {  // dd = 16: each opposite pair once
        const int m = l + 16;
        grp(ab_x, ab_y, ab_z,
            soa[0][0][m], soa[0][1][m], soa[0][2][m], soa[0][3][m], a0l, a0h);
        grp(cd_x, cd_y, cd_z,
            soa[1][0][m], soa[1][1][m], soa[1][2][m], soa[1][3][m], a2l, a2h);
    }

    // Row charges applied once; lane -> warp -> CTA reduction
    float s = sq[0] * (a0l + a1l);
    s = fmaf(sq[1], a0h, s);
    s = fmaf(sq[2], a1h + a2l, s);
    s = fmaf(sq[3], a2h, s);
#pragma unroll
    for (int o = 16; o > 0; o >>= 1)
        s += __shfl_xor_sync(0xFFFFFFFFu, s, o);
    if (l == 0) warp_sum[w] = s;
    __syncthreads();
    if (threadIdx.x == 0)
        out[fid] = (warp_sum[0] + warp_sum[1]) + (warp_sum[2] + warp_sum[3]);
}

extern "C" void kernel_launch(void* const* d_in, const int* in_sizes, int n_in,
                              void* d_out, int out_size) {
    const float* positions = (const float*)d_in[0];  // [N,3] f32
    const float* charges   = (const float*)d_in[1];  // [N]   f32
    float* out = (float*)d_out;                      // [B]   f32

    const int num_frames = out_size;
    interacting_sites_kernel<<<num_frames, S_SITES>>>(positions, charges, out);
}

// round 6
// speedup vs baseline: 1.1293x; 1.1293x over previous
#include <cuda_runtime.h>
#include <cstdint>

// InteractingSites: per-frame all-pairs soft-core Coulomb — SHUFFLE edition.
//
// energy[f] = sum_{i<j} q_i q_j * rsqrt(|p_i-p_j|^2 + 1e-6)
//
// CTA = 1 frame = 4 warps x 32. Sites tiled T0..T3 (32 each); lane l holds
// T0[l]..T3[l] in registers. NO shared-memory site tables: j-sites are
// delivered by __shfl_sync rotation (crossbar-free).
//
// Enumeration (each unordered pair exactly once), split across 4 warps:
//  Rectangles (6144 pairs): rotation r = 0..31, lane l does the 6 tile combos
//    (Ta[l], Tb[(l+r)&31]) for a<b.  Warp w: r in [8w, 8w+8).
//  Triangles (1984 pairs): per tile k, (Tk[l], Tk[(l+dd)&31]),
//    dd = 1..15 each once + dd = 16 masked to lanes 0..15.
//    Warps 0..2: dd in [4w+1, 4w+5); warp 3: dd 13,14,15,16(masked).
//
// Charge factoring: acc[a] += q_j * rsqrt(d2+eps); row charge q_a applied once
// at the end:  E_lane = sum_a sq[a]*acc[a].

#define S_SITES 128
#define EPS_SOFT 1e-6f
#define FULLMASK 0xFFFFFFFFu

__device__ __forceinline__ float frsqrt(float x) {
    float r;
    asm("rsqrt.approx.f32 %0, %1;" : "=f"(r) : "f"(x));
    return r;
}

// rsqrt(|a-j|^2 + eps)
__device__ __forceinline__ float pterm(float ax, float ay, float az,
                                       float jx, float jy, float jz) {
    float dx = ax - jx;
    float dy = ay - jy;
    float dz = az - jz;
    float r2 = fmaf(dx, dx, fmaf(dy, dy, fmaf(dz, dz, EPS_SOFT)));
    return frsqrt(r2);
}

__global__ __launch_bounds__(S_SITES)
void interacting_sites_kernel(const float* __restrict__ positions,
                              const float* __restrict__ charges,
                              float* __restrict__ out) {
    __shared__ float warp_sum[4];

    const int fid = blockIdx.x;
    const int w = threadIdx.x >> 5;
    const int l = threadIdx.x & 31;

    // Lane's 4 sites (one per tile), straight from global
    const long long base = (long long)fid * S_SITES;
    float sx[4], sy[4], sz[4], sq[4];
#pragma unroll
    for (int k = 0; k < 4; ++k) {
        const long long idx = base + k * 32 + l;
        const float* p = positions + idx * 3;
        sx[k] = p[0];
        sy[k] = p[1];
        sz[k] = p[2];
        sq[k] = charges[idx];
    }

    float acc0 = 0.f, acc1 = 0.f, acc2 = 0.f, acc3 = 0.f;

    // ── Rectangles: warp w handles rotations r in [8w, 8w+8) ──
    // __shfl_sync wraps srcLane mod 32, so pass l + r directly.
#pragma unroll
    for (int i = 0; i < 8; ++i) {
        const int src = l + (w << 3) + i;

        const float j1x = __shfl_sync(FULLMASK, sx[1], src);
        const float j1y = __shfl_sync(FULLMASK, sy[1], src);
        const float j1z = __shfl_sync(FULLMASK, sz[1], src);
        const float j1q = __shfl_sync(FULLMASK, sq[1], src);
        const float j2x = __shfl_sync(FULLMASK, sx[2], src);
        const float j2y = __shfl_sync(FULLMASK, sy[2], src);
        const float j2z = __shfl_sync(FULLMASK, sz[2], src);
        const float j2q = __shfl_sync(FULLMASK, sq[2], src);
        const float j3x = __shfl_sync(FULLMASK, sx[3], src);
        const float j3y = __shfl_sync(FULLMASK, sy[3], src);
        const float j3z = __shfl_sync(FULLMASK, sz[3], src);
        const float j3q = __shfl_sync(FULLMASK, sq[3], src);

        // 6 tile combos (a<b): j charge weighted into row-tile accumulator
        acc0 = fmaf(j1q, pterm(sx[0], sy[0], sz[0], j1x, j1y, j1z), acc0);
        acc0 = fmaf(j2q, pterm(sx[0], sy[0], sz[0], j2x, j2y, j2z), acc0);
        acc0 = fmaf(j3q, pterm(sx[0], sy[0], sz[0], j3x, j3y, j3z), acc0);
        acc1 = fmaf(j2q, pterm(sx[1], sy[1], sz[1], j2x, j2y, j2z), acc1);
        acc1 = fmaf(j3q, pterm(sx[1], sy[1], sz[1], j3x, j3y, j3z), acc1);
        acc2 = fmaf(j3q, pterm(sx[2], sy[2], sz[2], j3x, j3y, j3z), acc2);
    }

    // ── Triangles: warps 0..2 take dd in [4w+1, 4w+5); warp 3: 13,14,15,16m ──
#pragma unroll
    for (int i = 0; i < 4; ++i) {
        const int dd = (w << 2) + 1 + i;   // warp3 reaches dd=16
        const int src = l + dd;

        const float t0x = __shfl_sync(FULLMASK, sx[0], src);
        const float t0y = __shfl_sync(FULLMASK, sy[0], src);
        const float t0z = __shfl_sync(FULLMASK, sz[0], src);
        const float t0q = __shfl_sync(FULLMASK, sq[0], src);
        const float t1x = __shfl_sync(FULLMASK, sx[1], src);
        const float t1y = __shfl_sync(FULLMASK, sy[1], src);
        const float t1z = __shfl_sync(FULLMASK, sz[1], src);
        const float t1q = __shfl_sync(FULLMASK, sq[1], src);
        const float t2x = __shfl_sync(FULLMASK, sx[2], src);
        const float t2y = __shfl_sync(FULLMASK, sy[2], src);
        const float t2z = __shfl_sync(FULLMASK, sz[2], src);
        const float t2q = __shfl_sync(FULLMASK, sq[2], src);
        const float t3x = __shfl_sync(FULLMASK, sx[3], src);
        const float t3y = __shfl_sync(FULLMASK, sy[3], src);
        const float t3z = __shfl_sync(FULLMASK, sz[3], src);
        const float t3q = __shfl_sync(FULLMASK, sq[3], src);

        // dd=16 pairs (l, l+16) would be double-counted: mask to lanes 0..15
        if (dd < 16 || l < 16) {
            acc0 = fmaf(t0q, pterm(sx[0], sy[0], sz[0], t0x, t0y, t0z), acc0);
            acc1 = fmaf(t1q, pterm(sx[1], sy[1], sz[1], t1x, t1y, t1z), acc1);
            acc2 = fmaf(t2q, pterm(sx[2], sy[2], sz[2], t2x, t2y, t2z), acc2);
            acc3 = fmaf(t3q, pterm(sx[3], sy[3], sz[3], t3x, t3y, t3z), acc3);
        }
    }

    // Row charges applied once; lane -> warp -> CTA reduction
    float s = sq[0] * acc0;
    s = fmaf(sq[1], acc1, s);
    s = fmaf(sq[2], acc2, s);
    s = fmaf(sq[3], acc3, s);
#pragma unroll
    for (int o = 16; o > 0; o >>= 1)
        s += __shfl_xor_sync(FULLMASK, s, o);
    if (l == 0) warp_sum[w] = s;
    __syncthreads();
    if (threadIdx.x == 0)
        out[fid] = (warp_sum[0] + warp_sum[1]) + (warp_sum[2] + warp_sum[3]);
}

extern "C" void kernel_launch(void* const* d_in, const int* in_sizes, int n_in,
                              void* d_out, int out_size) {
    const float* positions = (const float*)d_in[0];  // [N,3] f32
    const float* charges   = (const float*)d_in[1];  // [N]   f32
    float* out = (float*)d_out;                      // [B]   f32

    const int num_frames = out_size;
    interacting_sites_kernel<<<num_frames, S_SITES>>>(positions, charges, out);
}